// round 8
// baseline (speedup 1.0000x reference)
#include <cuda_runtime.h>
#include <cuda_fp16.h>

#define NMAX 100000
#define HD 32
#define CAP 80

typedef unsigned long long ull;

// ---------------- scratch (static __device__, no allocation) ----------------
__device__ __align__(16) float  d_T[NMAX * HD];   // fp32 per-node transform [V,h]@W_top
__device__ __align__(16) float  d_u[NMAX * HD];   // h @ W_n_top (pre-relu node update)
__device__ float2 d_V[NMAX];                      // running V
__device__ __align__(16) uint4  d_E[(long)NMAX * CAP]; // {soff(=s*128), mask, h2(ef01), h2(ef23)}
__device__ int    d_cursor[NMAX];                 // per-receiver count (atomic)
__device__ __align__(16) float4 d_S4[NMAX];       // sum(mask*ef) per receiver
__device__ float  d_Smask[NMAX];                  // sum(mask) per receiver
__device__ float  d_pool[HD];                     // atomic pooled sum of h
__device__ float  d_g[HD];                        // global supernode state
__device__ float  d_c[HD];                        // g@W_n_bot + b_n (per layer)
__device__ float  d_A2[2 * HD];                   // init affine map rows
__device__ float  d_c0[HD];                       // init affine bias

__device__ __forceinline__ unsigned packh2(float a, float b) {
    __half2 h = __floats2half2_rn(a, b);
    return *reinterpret_cast<unsigned*>(&h);
}
__device__ __forceinline__ float2 unpackh2(unsigned u) {
    __half2 h = *reinterpret_cast<__half2*>(&u);
    return __half22float2(h);
}
__device__ __forceinline__ ull bcast64(float a) {        // {a,a} packed
    ull r; asm("mov.b64 %0, {%1, %1};" : "=l"(r) : "f"(a)); return r;
}
__device__ __forceinline__ void fma2(ull& acc, ull a, ull b) {
    asm("fma.rn.f32x2 %0, %1, %2, %0;" : "+l"(acc) : "l"(a), "l"(b));
}
__device__ __forceinline__ float2 unpack64(ull v) {
    float2 f; asm("mov.b64 {%0, %1}, %2;" : "=f"(f.x), "=f"(f.y) : "l"(v)); return f;
}
__device__ __forceinline__ ull add2(ull a, ull b) {
    ull r; asm("add.rn.f32x2 %0, %1, %2;" : "=l"(r) : "l"(a), "l"(b)); return r;
}

// ---------------- zero + init-affine prep ----------------
__global__ void k_zero(const float* __restrict__ W_in, const float* __restrict__ b_in,
                       const float* __restrict__ W_msg, int N) {
    int i = blockIdx.x * blockDim.x + threadIdx.x;
    if (i < N) d_cursor[i] = 0;
    if (blockIdx.x == 0 && threadIdx.x < HD) {
        int j = threadIdx.x;
        d_g[j] = 0.f; d_pool[j] = 0.f;
        const float* Wt = W_msg;       // layer 0 top rows (34 x 32)
        float c0 = Wt[j];              // V0=(1,0) -> + Wt[0][j]
        float a0 = 0.f, a1 = 0.f;
        for (int k = 0; k < HD; k++) {
            float wt = Wt[(2 + k) * HD + j];
            c0 += b_in[k] * wt;
            a0 += W_in[k] * wt;
            a1 += W_in[HD + k] * wt;
        }
        d_A2[j] = a0; d_A2[HD + j] = a1; d_c0[j] = c0;
    }
}

// ---------------- bucket fill: 1 atomic + one 16B store per edge ----------------
__device__ __forceinline__ void fill_one(int s, int r, float m, float4 f) {
    int pos = atomicAdd(&d_cursor[r], 1);
    if (pos < CAP) {
        uint4 ent;
        ent.x = ((unsigned)s) << 7;        // byte offset of fp32 T row
        ent.y = __float_as_uint(m);
        ent.z = packh2(f.x, f.y);
        ent.w = packh2(f.z, f.w);
        d_E[(long)r * CAP + pos] = ent;
    }
}

__global__ void k_fill(const int* __restrict__ send, const int* __restrict__ recv,
                       const float* __restrict__ mask, const float4* __restrict__ ef,
                       int E) {
    int base = (blockIdx.x * blockDim.x + threadIdx.x) * 8;
    if (base + 8 <= E) {
        #pragma unroll
        for (int q = 0; q < 2; q++) {
            int b = base + q * 4;
            int4 s = *(const int4*)(send + b);
            int4 r = *(const int4*)(recv + b);
            float4 m = *(const float4*)(mask + b);
            float4 f0 = ef[b], f1 = ef[b + 1], f2 = ef[b + 2], f3 = ef[b + 3];
            fill_one(s.x, r.x, m.x, f0);
            fill_one(s.y, r.y, m.y, f1);
            fill_one(s.z, r.z, m.z, f2);
            fill_one(s.w, r.w, m.w, f3);
        }
    } else {
        for (int e = base; e < E; e++)
            fill_one(send[e], recv[e], mask[e], ef[e]);
    }
}

// init: T0 = pq.x*A0 + pq.y*A1 + c0 (affine), V0=(1,0). Thread per (node, dim pair).
__global__ void k_init(const float2* __restrict__ PQ, int N) {
    __shared__ float sA0[HD], sA1[HD], sc0[HD];
    if (threadIdx.x < HD) {
        sA0[threadIdx.x] = d_A2[threadIdx.x];
        sA1[threadIdx.x] = d_A2[HD + threadIdx.x];
        sc0[threadIdx.x] = d_c0[threadIdx.x];
    }
    __syncthreads();
    int gid = blockIdx.x * blockDim.x + threadIdx.x;
    int node = gid >> 4, sub = gid & 15;
    if (node >= N) return;
    float2 pq = PQ[node];
    int d0 = 2 * sub;
    float t0 = pq.x * sA0[d0] + pq.y * sA1[d0] + sc0[d0];
    float t1 = pq.x * sA0[d0 + 1] + pq.y * sA1[d0 + 1] + sc0[d0 + 1];
    *(float2*)&d_T[node * HD + d0] = make_float2(t0, t1);
    if (sub == 0) d_V[node] = make_float2(1.f, 0.f);
}

// shared epilogue: combine halves, apply S4 message term, relu, u-GEMV (FFMA2), pool
__device__ __forceinline__ void agg_epilogue(
    int w, int lane, int half, int d0, int r, bool valid,
    float s0, float s1, float sx, float sy, float sz, float sw, float sm,
    const float* sWb, const float* sb, const float* sWn,
    float sh_h[8][HD]) {
    float h0 = 0.f, h1 = 0.f;
    if (valid) {
        s0 += __shfl_xor_sync(~0u, s0, 16);
        s1 += __shfl_xor_sync(~0u, s1, 16);
        int d1 = d0 + 1;
        s0 += sx * sWb[d0] + sy * sWb[HD + d0] + sz * sWb[2 * HD + d0] +
              sw * sWb[3 * HD + d0] + sm * sb[d0];
        s1 += sx * sWb[d1] + sy * sWb[HD + d1] + sz * sWb[2 * HD + d1] +
              sw * sWb[3 * HD + d1] + sm * sb[d1];
        h0 = fmaxf(s0, 0.f);
        h1 = fmaxf(s1, 0.f);
    }
    if (lane < 16) *(float2*)&sh_h[w][d0] = valid ? make_float2(h0, h1)
                                                  : make_float2(0.f, 0.f);
    __syncwarp();
    if (valid) {
        ull uacc = 0;
        int kb = half * 16;
        #pragma unroll
        for (int kk = 0; kk < 16; kk++) {
            ull hh = bcast64(sh_h[w][kb + kk]);
            ull wv = *(const ull*)&sWn[(kb + kk) * HD + d0];
            fma2(uacc, wv, hh);
        }
        float2 u = unpack64(uacc);
        u.x += __shfl_xor_sync(~0u, u.x, 16);
        u.y += __shfl_xor_sync(~0u, u.y, 16);
        if (lane < 16) *(float2*)&d_u[r * HD + d0] = u;
    }
    __syncthreads();
    if (w == 0) {
        float ps = 0.f;
        #pragma unroll
        for (int q = 0; q < 8; q++) ps += sh_h[q][lane];
        atomicAdd(&d_pool[lane], ps);
    }
}

// layer-0 aggregation: full entries; computes S4/Smask inline and stores them
__global__ void __launch_bounds__(256) k_agg0(
        const float* __restrict__ W_msg, const float* __restrict__ b_msg,
        const float* __restrict__ W_n, int N) {
    __shared__ float sWb[4 * HD], sb[HD], sWn[HD * HD];
    __shared__ float sh_h[8][HD];
    for (int i = threadIdx.x; i < 4 * HD; i += blockDim.x) sWb[i] = W_msg[34 * HD + i];
    for (int i = threadIdx.x; i < HD; i += blockDim.x) sb[i] = b_msg[i];
    for (int i = threadIdx.x; i < HD * HD; i += blockDim.x) sWn[i] = W_n[i];
    __syncthreads();
    int w = threadIdx.x >> 5;
    int lane = threadIdx.x & 31;
    int half = lane >> 4, sub = lane & 15;
    int d0 = 2 * sub;
    int r = blockIdx.x * 8 + w;
    bool valid = r < N;
    float sx = 0.f, sy = 0.f, sz = 0.f, sw = 0.f, sm = 0.f;
    ull accA = 0, accB = 0;
    if (valid) {
        const uint4* Eb = d_E + (long)r * CAP;
        const char* Tb = (const char*)d_T;
        int subOff = sub * 8;
        int cnt = min(d_cursor[r], CAP);
        int p = 0;
        for (; p + 4 <= cnt; p += 4) {
            uint4 eA = Eb[p + half];
            uint4 eB = Eb[p + 2 + half];
            float mA = __uint_as_float(eA.y);
            float mB = __uint_as_float(eB.y);
            ull tA = *(const ull*)(Tb + eA.x + subOff);
            ull tB = *(const ull*)(Tb + eB.x + subOff);
            fma2(accA, tA, bcast64(mA));
            fma2(accB, tB, bcast64(mB));
            float2 fA01 = unpackh2(eA.z), fA23 = unpackh2(eA.w);
            float2 fB01 = unpackh2(eB.z), fB23 = unpackh2(eB.w);
            sx += mA * fA01.x + mB * fB01.x;
            sy += mA * fA01.y + mB * fB01.y;
            sz += mA * fA23.x + mB * fB23.x;
            sw += mA * fA23.y + mB * fB23.y;
            sm += mA + mB;
        }
        if (p + 2 <= cnt) {
            uint4 eA = Eb[p + half];
            float mA = __uint_as_float(eA.y);
            ull tA = *(const ull*)(Tb + eA.x + subOff);
            fma2(accA, tA, bcast64(mA));
            float2 fA01 = unpackh2(eA.z), fA23 = unpackh2(eA.w);
            sx += mA * fA01.x; sy += mA * fA01.y;
            sz += mA * fA23.x; sw += mA * fA23.y;
            sm += mA;
            p += 2;
        }
        if (p < cnt) {                     // single tail: half0 only
            uint4 e = Eb[p];
            float m = __uint_as_float(e.y);
            if (!half) {
                ull t = *(const ull*)(Tb + e.x + subOff);
                fma2(accB, t, bcast64(m));
                float2 f01 = unpackh2(e.z), f23 = unpackh2(e.w);
                sx += m * f01.x; sy += m * f01.y;
                sz += m * f23.x; sw += m * f23.y;
                sm += m;
            }
        }
        sx += __shfl_xor_sync(~0u, sx, 16);
        sy += __shfl_xor_sync(~0u, sy, 16);
        sz += __shfl_xor_sync(~0u, sz, 16);
        sw += __shfl_xor_sync(~0u, sw, 16);
        sm += __shfl_xor_sync(~0u, sm, 16);
        if (lane == 0) {
            d_S4[r] = make_float4(sx, sy, sz, sw);
            d_Smask[r] = sm;
        }
    }
    float2 s = unpack64(add2(accA, accB));
    agg_epilogue(w, lane, half, d0, r, valid, s.x, s.y,
                 sx, sy, sz, sw, sm, sWb, sb, sWn, sh_h);
}

// layers 1-2 aggregation: uses stored S4/Smask; 8B entry loads
__global__ void __launch_bounds__(256) k_agg(
        const float* __restrict__ W_msg, const float* __restrict__ b_msg,
        const float* __restrict__ W_n, int l, int N) {
    __shared__ float sWb[4 * HD], sb[HD], sWn[HD * HD];
    __shared__ float sh_h[8][HD];
    const float* Wl = W_msg + l * 38 * HD;
    const float* Wn = W_n + l * 64 * HD;
    for (int i = threadIdx.x; i < 4 * HD; i += blockDim.x) sWb[i] = Wl[34 * HD + i];
    for (int i = threadIdx.x; i < HD; i += blockDim.x) sb[i] = b_msg[l * HD + i];
    for (int i = threadIdx.x; i < HD * HD; i += blockDim.x) sWn[i] = Wn[i];
    __syncthreads();
    int w = threadIdx.x >> 5;
    int lane = threadIdx.x & 31;
    int half = lane >> 4, sub = lane & 15;
    int d0 = 2 * sub;
    int r = blockIdx.x * 8 + w;
    bool valid = r < N;
    float sx = 0.f, sy = 0.f, sz = 0.f, sw = 0.f, sm = 0.f;
    ull accA = 0, accB = 0;
    if (valid) {
        const uint2* Eb = (const uint2*)(d_E + (long)r * CAP);  // entry i low 8B at [2i]
        const char* Tb = (const char*)d_T;
        int subOff = sub * 8;
        int cnt = min(d_cursor[r], CAP);
        int p = 0;
        for (; p + 4 <= cnt; p += 4) {
            uint2 eA = Eb[(p + half) * 2];
            uint2 eB = Eb[(p + 2 + half) * 2];
            ull tA = *(const ull*)(Tb + eA.x + subOff);
            ull tB = *(const ull*)(Tb + eB.x + subOff);
            fma2(accA, tA, bcast64(__uint_as_float(eA.y)));
            fma2(accB, tB, bcast64(__uint_as_float(eB.y)));
        }
        if (p + 2 <= cnt) {
            uint2 eA = Eb[(p + half) * 2];
            ull tA = *(const ull*)(Tb + eA.x + subOff);
            fma2(accA, tA, bcast64(__uint_as_float(eA.y)));
            p += 2;
        }
        if (p < cnt) {
            uint2 e = Eb[p * 2];
            if (!half) {
                ull t = *(const ull*)(Tb + e.x + subOff);
                fma2(accB, t, bcast64(__uint_as_float(e.y)));
            }
        }
        float4 s4 = d_S4[r];
        sx = s4.x; sy = s4.y; sz = s4.z; sw = s4.w;
        sm = d_Smask[r];
    }
    float2 s = unpack64(add2(accA, accB));
    agg_epilogue(w, lane, half, d0, r, valid, s.x, s.y,
                 sx, sy, sz, sw, sm, sWb, sb, sWn, sh_h);
}

// global supernode update + precompute c = g_new @ W_n[32:64] + b_n ; re-zero pool
__global__ void k_g(const float* __restrict__ W_g, const float* __restrict__ b_g,
                    const float* __restrict__ W_n, const float* __restrict__ b_n,
                    int l, int N) {
    int j = threadIdx.x;  // 32 threads
    float p = d_pool[j] / (float)N;
    d_pool[j] = 0.f;
    float gold = d_g[j];
    const float* Wg = W_g + l * 64 * HD;
    float acc = b_g[l * HD + j];
    #pragma unroll
    for (int k = 0; k < HD; k++) {
        acc += __shfl_sync(~0u, gold, k) * Wg[k * HD + j];
        acc += __shfl_sync(~0u, p, k) * Wg[(HD + k) * HD + j];
    }
    float gn = fmaxf(acc, 0.f);
    d_g[j] = gn;
    const float* Wn = W_n + l * 64 * HD;
    float c = b_n[l * HD + j];
    #pragma unroll
    for (int k = 0; k < HD; k++)
        c += __shfl_sync(~0u, gn, k) * Wn[(HD + k) * HD + j];
    d_c[j] = c;
}

// node update: hn = relu(u + c); V += hn@W_out + b_out; T_next = [V,hn]@W_top(l+1)
__global__ void k_node(const float* __restrict__ W_out, const float* __restrict__ b_out,
                       const float* __restrict__ W_msg,
                       int l, int N, int last, float2* __restrict__ outV) {
    __shared__ float sWo[HD * 2], sWt[34 * HD], sc[HD];
    for (int i = threadIdx.x; i < HD * 2; i += blockDim.x) sWo[i] = W_out[l * HD * 2 + i];
    if (!last) {
        const float* Wt = W_msg + (l + 1) * 38 * HD;
        for (int i = threadIdx.x; i < 34 * HD; i += blockDim.x) sWt[i] = Wt[i];
    }
    for (int i = threadIdx.x; i < HD; i += blockDim.x) sc[i] = d_c[i];
    __syncthreads();
    int r = (blockIdx.x * blockDim.x + threadIdx.x) >> 5;
    int lane = threadIdx.x & 31;
    if (r >= N) return;
    float hn = fmaxf(d_u[r * HD + lane] + sc[lane], 0.f);
    float v0 = hn * sWo[lane * 2 + 0];
    float v1 = hn * sWo[lane * 2 + 1];
    #pragma unroll
    for (int o = 16; o; o >>= 1) {
        v0 += __shfl_xor_sync(~0u, v0, o);
        v1 += __shfl_xor_sync(~0u, v1, o);
    }
    float2 v = d_V[r];
    v.x += v0 + b_out[l * 2 + 0];
    v.y += v1 + b_out[l * 2 + 1];
    if (last) {
        if (lane == 0) outV[r] = v;
    } else {
        if (lane == 0) d_V[r] = v;
        int half = lane >> 4, sub = lane & 15;
        int d0 = 2 * sub, d1 = d0 + 1;
        int kb = half * 16;
        ull tacc = 0;
        #pragma unroll
        for (int kk = 0; kk < 16; kk++) {
            float hk = __shfl_sync(~0u, hn, kb + kk);
            ull wv = *(const ull*)&sWt[(2 + kb + kk) * HD + d0];
            fma2(tacc, wv, bcast64(hk));
        }
        float2 t = unpack64(tacc);
        t.x += __shfl_xor_sync(~0u, t.x, 16);
        t.y += __shfl_xor_sync(~0u, t.y, 16);
        t.x += v.x * sWt[d0] + v.y * sWt[HD + d0];
        t.y += v.x * sWt[d1] + v.y * sWt[HD + d1];
        if (lane < 16)
            *(float2*)&d_T[r * HD + d0] = t;
    }
}

// ---------------- launch ----------------
extern "C" void kernel_launch(void* const* d_in, const int* in_sizes, int n_in,
                              void* d_out, int out_size) {
    const float2* PQ    = (const float2*)d_in[0];
    const int*    send  = (const int*)d_in[1];
    const int*    recv  = (const int*)d_in[2];
    const float4* ef    = (const float4*)d_in[3];
    const float*  mask  = (const float*)d_in[4];
    const float*  W_in  = (const float*)d_in[5];
    const float*  b_in  = (const float*)d_in[6];
    const float*  W_msg = (const float*)d_in[7];
    const float*  b_msg = (const float*)d_in[8];
    const float*  W_g   = (const float*)d_in[9];
    const float*  b_g   = (const float*)d_in[10];
    const float*  W_n   = (const float*)d_in[11];
    const float*  b_n   = (const float*)d_in[12];
    const float*  W_out = (const float*)d_in[13];
    const float*  b_out = (const float*)d_in[14];

    int N = in_sizes[0] / 2;
    int E = in_sizes[1];
    int nwb = (N + 7) / 8;          // warp-per-node kernels (256 thr)
    int eb8 = (E + 2047) / 2048;    // 8 edges/thread

    k_zero<<<(N + 255) / 256, 256>>>(W_in, b_in, W_msg, N);
    k_fill<<<eb8, 256>>>(send, recv, mask, ef, E);
    k_init<<<(N * 16 + 255) / 256, 256>>>(PQ, N);

    k_agg0<<<nwb, 256>>>(W_msg, b_msg, W_n, N);
    k_g<<<1, 32>>>(W_g, b_g, W_n, b_n, 0, N);
    k_node<<<nwb, 256>>>(W_out, b_out, W_msg, 0, N, 0, (float2*)d_out);

    for (int l = 1; l < 3; l++) {
        k_agg<<<nwb, 256>>>(W_msg, b_msg, W_n, l, N);
        k_g<<<1, 32>>>(W_g, b_g, W_n, b_n, l, N);
        k_node<<<nwb, 256>>>(W_out, b_out, W_msg, l, N, l == 2, (float2*)d_out);
    }
}

// round 9
// speedup vs baseline: 1.0390x; 1.0390x over previous
#include <cuda_runtime.h>
#include <cuda_fp16.h>

#define NMAX 100000
#define HD 32
#define CAP 80

typedef unsigned long long ull;

// ---------------- scratch (static __device__, no allocation) ----------------
__device__ __align__(16) __half d_Th[NMAX * HD];  // fp16 per-node transform [V,h]@W_top
__device__ __align__(16) float  d_u[NMAX * HD];   // h @ W_n_top (pre-relu node update)
__device__ float2 d_V[NMAX];                      // running V
__device__ __align__(16) uint4  d_E[(long)NMAX * CAP]; // {soff(=s*64), mask, h2(ef01), h2(ef23)}
__device__ int    d_cursor[NMAX];                 // per-receiver count (atomic)
__device__ __align__(16) float4 d_S4[NMAX];       // sum(mask*ef) per receiver
__device__ float  d_Smask[NMAX];                  // sum(mask) per receiver
__device__ float  d_pool[HD];                     // atomic pooled sum of h
__device__ float  d_g[HD];                        // global supernode state
__device__ float  d_c[HD];                        // g@W_n_bot + b_n (per layer)
__device__ float  d_A2[2 * HD];                   // init affine map rows
__device__ float  d_c0[HD];                       // init affine bias

__device__ __forceinline__ unsigned packh2(float a, float b) {
    __half2 h = __floats2half2_rn(a, b);
    return *reinterpret_cast<unsigned*>(&h);
}
__device__ __forceinline__ float2 unpackh2(unsigned u) {
    __half2 h = *reinterpret_cast<__half2*>(&u);
    return __half22float2(h);
}
__device__ __forceinline__ ull bcast64(float a) {        // {a,a} packed
    ull r; asm("mov.b64 %0, {%1, %1};" : "=l"(r) : "f"(a)); return r;
}
__device__ __forceinline__ void fma2(ull& acc, ull a, ull b) {
    asm("fma.rn.f32x2 %0, %1, %2, %0;" : "+l"(acc) : "l"(a), "l"(b));
}
__device__ __forceinline__ float2 unpack64(ull v) {
    float2 f; asm("mov.b64 {%0, %1}, %2;" : "=f"(f.x), "=f"(f.y) : "l"(v)); return f;
}

// ---------------- zero + init-affine prep ----------------
__global__ void k_zero(const float* __restrict__ W_in, const float* __restrict__ b_in,
                       const float* __restrict__ W_msg, int N) {
    int i = blockIdx.x * blockDim.x + threadIdx.x;
    if (i < N) d_cursor[i] = 0;
    if (blockIdx.x == 0 && threadIdx.x < HD) {
        int j = threadIdx.x;
        d_g[j] = 0.f; d_pool[j] = 0.f;
        const float* Wt = W_msg;       // layer 0 top rows (34 x 32)
        float c0 = Wt[j];              // V0=(1,0) -> + Wt[0][j]
        float a0 = 0.f, a1 = 0.f;
        for (int k = 0; k < HD; k++) {
            float wt = Wt[(2 + k) * HD + j];
            c0 += b_in[k] * wt;
            a0 += W_in[k] * wt;
            a1 += W_in[HD + k] * wt;
        }
        d_A2[j] = a0; d_A2[HD + j] = a1; d_c0[j] = c0;
    }
}

// ---------------- bucket fill: 1 atomic + one 16B store per edge ----------------
__device__ __forceinline__ void fill_one(int s, int r, float m, float4 f) {
    int pos = atomicAdd(&d_cursor[r], 1);
    if (pos < CAP) {
        uint4 ent;
        ent.x = ((unsigned)s) << 6;        // byte offset of fp16 T row (32*2B)
        ent.y = __float_as_uint(m);
        ent.z = packh2(f.x, f.y);
        ent.w = packh2(f.z, f.w);
        d_E[(long)r * CAP + pos] = ent;
    }
}

__global__ void k_fill(const int* __restrict__ send, const int* __restrict__ recv,
                       const float* __restrict__ mask, const float4* __restrict__ ef,
                       int E) {
    int base = (blockIdx.x * blockDim.x + threadIdx.x) * 8;
    if (base + 8 <= E) {
        #pragma unroll
        for (int q = 0; q < 2; q++) {
            int b = base + q * 4;
            int4 s = *(const int4*)(send + b);
            int4 r = *(const int4*)(recv + b);
            float4 m = *(const float4*)(mask + b);
            float4 f0 = ef[b], f1 = ef[b + 1], f2 = ef[b + 2], f3 = ef[b + 3];
            fill_one(s.x, r.x, m.x, f0);
            fill_one(s.y, r.y, m.y, f1);
            fill_one(s.z, r.z, m.z, f2);
            fill_one(s.w, r.w, m.w, f3);
        }
    } else {
        for (int e = base; e < E; e++)
            fill_one(send[e], recv[e], mask[e], ef[e]);
    }
}

// init: T0 = pq.x*A0 + pq.y*A1 + c0 (affine), V0=(1,0). Thread per (node, dim pair).
__global__ void k_init(const float2* __restrict__ PQ, int N) {
    __shared__ float sA0[HD], sA1[HD], sc0[HD];
    if (threadIdx.x < HD) {
        sA0[threadIdx.x] = d_A2[threadIdx.x];
        sA1[threadIdx.x] = d_A2[HD + threadIdx.x];
        sc0[threadIdx.x] = d_c0[threadIdx.x];
    }
    __syncthreads();
    int gid = blockIdx.x * blockDim.x + threadIdx.x;
    int node = gid >> 4, sub = gid & 15;
    if (node >= N) return;
    float2 pq = PQ[node];
    int d0 = 2 * sub;
    float t0 = pq.x * sA0[d0] + pq.y * sA1[d0] + sc0[d0];
    float t1 = pq.x * sA0[d0 + 1] + pq.y * sA1[d0 + 1] + sc0[d0 + 1];
    *(__half2*)&d_Th[node * HD + d0] = __floats2half2_rn(t0, t1);
    if (sub == 0) d_V[node] = make_float2(1.f, 0.f);
}

// shared epilogue: combine halves, apply S4 message term, relu, u-GEMV (FFMA2), pool
__device__ __forceinline__ void agg_epilogue(
    int w, int lane, int half, int d0, int r, bool valid,
    float s0, float s1, float sx, float sy, float sz, float sw, float sm,
    const float* sWb, const float* sb, const float* sWn,
    float sh_h[8][HD]) {
    float h0 = 0.f, h1 = 0.f;
    if (valid) {
        s0 += __shfl_xor_sync(~0u, s0, 16);
        s1 += __shfl_xor_sync(~0u, s1, 16);
        int d1 = d0 + 1;
        s0 += sx * sWb[d0] + sy * sWb[HD + d0] + sz * sWb[2 * HD + d0] +
              sw * sWb[3 * HD + d0] + sm * sb[d0];
        s1 += sx * sWb[d1] + sy * sWb[HD + d1] + sz * sWb[2 * HD + d1] +
              sw * sWb[3 * HD + d1] + sm * sb[d1];
        h0 = fmaxf(s0, 0.f);
        h1 = fmaxf(s1, 0.f);
    }
    if (lane < 16) *(float2*)&sh_h[w][d0] = valid ? make_float2(h0, h1)
                                                  : make_float2(0.f, 0.f);
    __syncwarp();
    if (valid) {
        ull uacc = 0;
        int kb = half * 16;
        #pragma unroll
        for (int kk = 0; kk < 16; kk++) {
            ull hh = bcast64(sh_h[w][kb + kk]);
            ull wv = *(const ull*)&sWn[(kb + kk) * HD + d0];
            fma2(uacc, wv, hh);
        }
        float2 u = unpack64(uacc);
        u.x += __shfl_xor_sync(~0u, u.x, 16);
        u.y += __shfl_xor_sync(~0u, u.y, 16);
        if (lane < 16) *(float2*)&d_u[r * HD + d0] = u;
    }
    __syncthreads();
    if (w == 0) {
        float ps = 0.f;
        #pragma unroll
        for (int q = 0; q < 8; q++) ps += sh_h[q][lane];
        atomicAdd(&d_pool[lane], ps);
    }
}

// layer-0 aggregation: full entries; 8-edge unroll (4 gathers in flight); inline S4
__global__ void __launch_bounds__(256) k_agg0(
        const float* __restrict__ W_msg, const float* __restrict__ b_msg,
        const float* __restrict__ W_n, int N) {
    __shared__ float sWb[4 * HD], sb[HD], sWn[HD * HD];
    __shared__ float sh_h[8][HD];
    for (int i = threadIdx.x; i < 4 * HD; i += blockDim.x) sWb[i] = W_msg[34 * HD + i];
    for (int i = threadIdx.x; i < HD; i += blockDim.x) sb[i] = b_msg[i];
    for (int i = threadIdx.x; i < HD * HD; i += blockDim.x) sWn[i] = W_n[i];
    __syncthreads();
    int w = threadIdx.x >> 5;
    int lane = threadIdx.x & 31;
    int half = lane >> 4, sub = lane & 15;
    int d0 = 2 * sub;
    int r = blockIdx.x * 8 + w;
    bool valid = r < N;
    float sx = 0.f, sy = 0.f, sz = 0.f, sw = 0.f, sm = 0.f;
    float a0 = 0.f, a1 = 0.f, b0 = 0.f, b1 = 0.f;
    float c0 = 0.f, c1 = 0.f, e0a = 0.f, e1a = 0.f;
    if (valid) {
        const uint4* Eb = d_E + (long)r * CAP;
        const char* Tb = (const char*)d_Th;
        int subOff = sub * 4;
        int cnt = min(d_cursor[r], CAP);
        int p = 0;
        for (; p + 8 <= cnt; p += 8) {
            uint4 q0 = Eb[p + half];
            uint4 q1 = Eb[p + 2 + half];
            uint4 q2 = Eb[p + 4 + half];
            uint4 q3 = Eb[p + 6 + half];
            float m0 = __uint_as_float(q0.y);
            float m1 = __uint_as_float(q1.y);
            float m2 = __uint_as_float(q2.y);
            float m3 = __uint_as_float(q3.y);
            float2 t0 = __half22float2(*(const __half2*)(Tb + q0.x + subOff));
            float2 t1 = __half22float2(*(const __half2*)(Tb + q1.x + subOff));
            float2 t2 = __half22float2(*(const __half2*)(Tb + q2.x + subOff));
            float2 t3 = __half22float2(*(const __half2*)(Tb + q3.x + subOff));
            a0 += m0 * t0.x; a1 += m0 * t0.y;
            b0 += m1 * t1.x; b1 += m1 * t1.y;
            c0 += m2 * t2.x; c1 += m2 * t2.y;
            e0a += m3 * t3.x; e1a += m3 * t3.y;
            float2 f0a = unpackh2(q0.z), f0b = unpackh2(q0.w);
            float2 f1a = unpackh2(q1.z), f1b = unpackh2(q1.w);
            float2 f2a = unpackh2(q2.z), f2b = unpackh2(q2.w);
            float2 f3a = unpackh2(q3.z), f3b = unpackh2(q3.w);
            sx += m0 * f0a.x + m1 * f1a.x + m2 * f2a.x + m3 * f3a.x;
            sy += m0 * f0a.y + m1 * f1a.y + m2 * f2a.y + m3 * f3a.y;
            sz += m0 * f0b.x + m1 * f1b.x + m2 * f2b.x + m3 * f3b.x;
            sw += m0 * f0b.y + m1 * f1b.y + m2 * f2b.y + m3 * f3b.y;
            sm += m0 + m1 + m2 + m3;
        }
        for (; p + 2 <= cnt; p += 2) {
            uint4 q0 = Eb[p + half];
            float m0 = __uint_as_float(q0.y);
            float2 t0 = __half22float2(*(const __half2*)(Tb + q0.x + subOff));
            a0 += m0 * t0.x; a1 += m0 * t0.y;
            float2 f0a = unpackh2(q0.z), f0b = unpackh2(q0.w);
            sx += m0 * f0a.x; sy += m0 * f0a.y;
            sz += m0 * f0b.x; sw += m0 * f0b.y;
            sm += m0;
        }
        if (p < cnt) {                     // single tail: half0 only
            uint4 q0 = Eb[p];
            float m0 = __uint_as_float(q0.y);
            if (!half) {
                float2 t0 = __half22float2(*(const __half2*)(Tb + q0.x + subOff));
                b0 += m0 * t0.x; b1 += m0 * t0.y;
                float2 f0a = unpackh2(q0.z), f0b = unpackh2(q0.w);
                sx += m0 * f0a.x; sy += m0 * f0a.y;
                sz += m0 * f0b.x; sw += m0 * f0b.y;
                sm += m0;
            }
        }
        sx += __shfl_xor_sync(~0u, sx, 16);
        sy += __shfl_xor_sync(~0u, sy, 16);
        sz += __shfl_xor_sync(~0u, sz, 16);
        sw += __shfl_xor_sync(~0u, sw, 16);
        sm += __shfl_xor_sync(~0u, sm, 16);
        if (lane == 0) {
            d_S4[r] = make_float4(sx, sy, sz, sw);
            d_Smask[r] = sm;
        }
    }
    agg_epilogue(w, lane, half, d0, r, valid,
                 (a0 + b0) + (c0 + e0a), (a1 + b1) + (c1 + e1a),
                 sx, sy, sz, sw, sm, sWb, sb, sWn, sh_h);
}

// layers 1-2 aggregation: stored S4/Smask; 8B entries; 8-edge unroll
__global__ void __launch_bounds__(256) k_agg(
        const float* __restrict__ W_msg, const float* __restrict__ b_msg,
        const float* __restrict__ W_n, int l, int N) {
    __shared__ float sWb[4 * HD], sb[HD], sWn[HD * HD];
    __shared__ float sh_h[8][HD];
    const float* Wl = W_msg + l * 38 * HD;
    const float* Wn = W_n + l * 64 * HD;
    for (int i = threadIdx.x; i < 4 * HD; i += blockDim.x) sWb[i] = Wl[34 * HD + i];
    for (int i = threadIdx.x; i < HD; i += blockDim.x) sb[i] = b_msg[l * HD + i];
    for (int i = threadIdx.x; i < HD * HD; i += blockDim.x) sWn[i] = Wn[i];
    __syncthreads();
    int w = threadIdx.x >> 5;
    int lane = threadIdx.x & 31;
    int half = lane >> 4, sub = lane & 15;
    int d0 = 2 * sub;
    int r = blockIdx.x * 8 + w;
    bool valid = r < N;
    float sx = 0.f, sy = 0.f, sz = 0.f, sw = 0.f, sm = 0.f;
    float a0 = 0.f, a1 = 0.f, b0 = 0.f, b1 = 0.f;
    float c0 = 0.f, c1 = 0.f, e0a = 0.f, e1a = 0.f;
    if (valid) {
        const uint2* Eb = (const uint2*)(d_E + (long)r * CAP);  // entry i low 8B at [2i]
        const char* Tb = (const char*)d_Th;
        int subOff = sub * 4;
        int cnt = min(d_cursor[r], CAP);
        int p = 0;
        for (; p + 8 <= cnt; p += 8) {
            uint2 q0 = Eb[(p + half) * 2];
            uint2 q1 = Eb[(p + 2 + half) * 2];
            uint2 q2 = Eb[(p + 4 + half) * 2];
            uint2 q3 = Eb[(p + 6 + half) * 2];
            float2 t0 = __half22float2(*(const __half2*)(Tb + q0.x + subOff));
            float2 t1 = __half22float2(*(const __half2*)(Tb + q1.x + subOff));
            float2 t2 = __half22float2(*(const __half2*)(Tb + q2.x + subOff));
            float2 t3 = __half22float2(*(const __half2*)(Tb + q3.x + subOff));
            float m0 = __uint_as_float(q0.y);
            float m1 = __uint_as_float(q1.y);
            float m2 = __uint_as_float(q2.y);
            float m3 = __uint_as_float(q3.y);
            a0 += m0 * t0.x; a1 += m0 * t0.y;
            b0 += m1 * t1.x; b1 += m1 * t1.y;
            c0 += m2 * t2.x; c1 += m2 * t2.y;
            e0a += m3 * t3.x; e1a += m3 * t3.y;
        }
        for (; p + 2 <= cnt; p += 2) {
            uint2 q0 = Eb[(p + half) * 2];
            float m0 = __uint_as_float(q0.y);
            float2 t0 = __half22float2(*(const __half2*)(Tb + q0.x + subOff));
            a0 += m0 * t0.x; a1 += m0 * t0.y;
        }
        if (p < cnt) {
            uint2 q0 = Eb[p * 2];
            if (!half) {
                float m0 = __uint_as_float(q0.y);
                float2 t0 = __half22float2(*(const __half2*)(Tb + q0.x + subOff));
                b0 += m0 * t0.x; b1 += m0 * t0.y;
            }
        }
        float4 s4 = d_S4[r];
        sx = s4.x; sy = s4.y; sz = s4.z; sw = s4.w;
        sm = d_Smask[r];
    }
    agg_epilogue(w, lane, half, d0, r, valid,
                 (a0 + b0) + (c0 + e0a), (a1 + b1) + (c1 + e1a),
                 sx, sy, sz, sw, sm, sWb, sb, sWn, sh_h);
}

// global supernode update + precompute c = g_new @ W_n[32:64] + b_n ; re-zero pool
__global__ void k_g(const float* __restrict__ W_g, const float* __restrict__ b_g,
                    const float* __restrict__ W_n, const float* __restrict__ b_n,
                    int l, int N) {
    int j = threadIdx.x;  // 32 threads
    float p = d_pool[j] / (float)N;
    d_pool[j] = 0.f;
    float gold = d_g[j];
    const float* Wg = W_g + l * 64 * HD;
    float acc = b_g[l * HD + j];
    #pragma unroll
    for (int k = 0; k < HD; k++) {
        acc += __shfl_sync(~0u, gold, k) * Wg[k * HD + j];
        acc += __shfl_sync(~0u, p, k) * Wg[(HD + k) * HD + j];
    }
    float gn = fmaxf(acc, 0.f);
    d_g[j] = gn;
    const float* Wn = W_n + l * 64 * HD;
    float c = b_n[l * HD + j];
    #pragma unroll
    for (int k = 0; k < HD; k++)
        c += __shfl_sync(~0u, gn, k) * Wn[(HD + k) * HD + j];
    d_c[j] = c;
}

// node update: hn = relu(u + c); V += hn@W_out + b_out; T_next = [V,hn]@W_top(l+1)
__global__ void k_node(const float* __restrict__ W_out, const float* __restrict__ b_out,
                       const float* __restrict__ W_msg,
                       int l, int N, int last, float2* __restrict__ outV) {
    __shared__ float sWo[HD * 2], sWt[34 * HD], sc[HD];
    for (int i = threadIdx.x; i < HD * 2; i += blockDim.x) sWo[i] = W_out[l * HD * 2 + i];
    if (!last) {
        const float* Wt = W_msg + (l + 1) * 38 * HD;
        for (int i = threadIdx.x; i < 34 * HD; i += blockDim.x) sWt[i] = Wt[i];
    }
    for (int i = threadIdx.x; i < HD; i += blockDim.x) sc[i] = d_c[i];
    __syncthreads();
    int r = (blockIdx.x * blockDim.x + threadIdx.x) >> 5;
    int lane = threadIdx.x & 31;
    if (r >= N) return;
    float hn = fmaxf(d_u[r * HD + lane] + sc[lane], 0.f);
    float v0 = hn * sWo[lane * 2 + 0];
    float v1 = hn * sWo[lane * 2 + 1];
    #pragma unroll
    for (int o = 16; o; o >>= 1) {
        v0 += __shfl_xor_sync(~0u, v0, o);
        v1 += __shfl_xor_sync(~0u, v1, o);
    }
    float2 v = d_V[r];
    v.x += v0 + b_out[l * 2 + 0];
    v.y += v1 + b_out[l * 2 + 1];
    if (last) {
        if (lane == 0) outV[r] = v;
    } else {
        if (lane == 0) d_V[r] = v;
        int half = lane >> 4, sub = lane & 15;
        int d0 = 2 * sub, d1 = d0 + 1;
        int kb = half * 16;
        ull tacc = 0;
        #pragma unroll
        for (int kk = 0; kk < 16; kk++) {
            float hk = __shfl_sync(~0u, hn, kb + kk);
            ull wv = *(const ull*)&sWt[(2 + kb + kk) * HD + d0];
            fma2(tacc, wv, bcast64(hk));
        }
        float2 t = unpack64(tacc);
        t.x += __shfl_xor_sync(~0u, t.x, 16);
        t.y += __shfl_xor_sync(~0u, t.y, 16);
        t.x += v.x * sWt[d0] + v.y * sWt[HD + d0];
        t.y += v.x * sWt[d1] + v.y * sWt[HD + d1];
        if (lane < 16)
            *(__half2*)&d_Th[r * HD + d0] = __floats2half2_rn(t.x, t.y);
    }
}

// ---------------- launch ----------------
extern "C" void kernel_launch(void* const* d_in, const int* in_sizes, int n_in,
                              void* d_out, int out_size) {
    const float2* PQ    = (const float2*)d_in[0];
    const int*    send  = (const int*)d_in[1];
    const int*    recv  = (const int*)d_in[2];
    const float4* ef    = (const float4*)d_in[3];
    const float*  mask  = (const float*)d_in[4];
    const float*  W_in  = (const float*)d_in[5];
    const float*  b_in  = (const float*)d_in[6];
    const float*  W_msg = (const float*)d_in[7];
    const float*  b_msg = (const float*)d_in[8];
    const float*  W_g   = (const float*)d_in[9];
    const float*  b_g   = (const float*)d_in[10];
    const float*  W_n   = (const float*)d_in[11];
    const float*  b_n   = (const float*)d_in[12];
    const float*  W_out = (const float*)d_in[13];
    const float*  b_out = (const float*)d_in[14];

    int N = in_sizes[0] / 2;
    int E = in_sizes[1];
    int nwb = (N + 7) / 8;          // warp-per-node kernels (256 thr)
    int eb8 = (E + 2047) / 2048;    // 8 edges/thread

    k_zero<<<(N + 255) / 256, 256>>>(W_in, b_in, W_msg, N);
    k_fill<<<eb8, 256>>>(send, recv, mask, ef, E);
    k_init<<<(N * 16 + 255) / 256, 256>>>(PQ, N);

    k_agg0<<<nwb, 256>>>(W_msg, b_msg, W_n, N);
    k_g<<<1, 32>>>(W_g, b_g, W_n, b_n, 0, N);
    k_node<<<nwb, 256>>>(W_out, b_out, W_msg, 0, N, 0, (float2*)d_out);

    for (int l = 1; l < 3; l++) {
        k_agg<<<nwb, 256>>>(W_msg, b_msg, W_n, l, N);
        k_g<<<1, 32>>>(W_g, b_g, W_n, b_n, l, N);
        k_node<<<nwb, 256>>>(W_out, b_out, W_msg, l, N, l == 2, (float2*)d_out);
    }
}

// round 10
// speedup vs baseline: 1.0600x; 1.0202x over previous
#include <cuda_runtime.h>
#include <cuda_fp16.h>

#define NMAX 100000
#define HD 32
#define CAP 80

typedef unsigned long long ull;

// ---------------- scratch (static __device__, no allocation) ----------------
__device__ __align__(16) __half d_Th[NMAX * HD];  // fp16 per-node transform [V,h]@W_top
__device__ __align__(16) float  d_u[NMAX * HD];   // h @ W_n_top (pre-relu node update)
__device__ float2 d_V[NMAX];                      // running V
__device__ __align__(16) uint4  d_E[(long)NMAX * CAP]; // {soff(=s*64), h2(m,m), h2(ef01), h2(ef23)}
__device__ int    d_cursor[NMAX];                 // per-receiver count (atomic)
__device__ __align__(16) float4 d_S4[NMAX];       // sum(mask*ef) per receiver
__device__ float  d_Smask[NMAX];                  // sum(mask) per receiver
__device__ float  d_pool[HD];                     // atomic pooled sum of h
__device__ float  d_g[HD];                        // global supernode state
__device__ float  d_c[HD];                        // g@W_n_bot + b_n (per layer)
__device__ float  d_A2[2 * HD];                   // init affine map rows
__device__ float  d_c0[HD];                       // init affine bias

__device__ __forceinline__ unsigned packh2(float a, float b) {
    __half2 h = __floats2half2_rn(a, b);
    return *reinterpret_cast<unsigned*>(&h);
}
__device__ __forceinline__ __half2 u2h(unsigned u) {
    return *reinterpret_cast<__half2*>(&u);
}
__device__ __forceinline__ ull bcast64(float a) {        // {a,a} packed
    ull r; asm("mov.b64 %0, {%1, %1};" : "=l"(r) : "f"(a)); return r;
}
__device__ __forceinline__ void fma2(ull& acc, ull a, ull b) {
    asm("fma.rn.f32x2 %0, %1, %2, %0;" : "+l"(acc) : "l"(a), "l"(b));
}
__device__ __forceinline__ float2 unpack64(ull v) {
    float2 f; asm("mov.b64 {%0, %1}, %2;" : "=f"(f.x), "=f"(f.y) : "l"(v)); return f;
}

// ---------------- zero + init-affine prep ----------------
__global__ void k_zero(const float* __restrict__ W_in, const float* __restrict__ b_in,
                       const float* __restrict__ W_msg, int N) {
    int i = blockIdx.x * blockDim.x + threadIdx.x;
    if (i < N) d_cursor[i] = 0;
    if (blockIdx.x == 0 && threadIdx.x < HD) {
        int j = threadIdx.x;
        d_g[j] = 0.f; d_pool[j] = 0.f;
        const float* Wt = W_msg;       // layer 0 top rows (34 x 32)
        float c0 = Wt[j];              // V0=(1,0) -> + Wt[0][j]
        float a0 = 0.f, a1 = 0.f;
        for (int k = 0; k < HD; k++) {
            float wt = Wt[(2 + k) * HD + j];
            c0 += b_in[k] * wt;
            a0 += W_in[k] * wt;
            a1 += W_in[HD + k] * wt;
        }
        d_A2[j] = a0; d_A2[HD + j] = a1; d_c0[j] = c0;
    }
}

// ---------------- bucket fill: 1 atomic + one 16B store per edge ----------------
__device__ __forceinline__ void fill_one(int s, int r, float m, float4 f) {
    int pos = atomicAdd(&d_cursor[r], 1);
    if (pos < CAP) {
        uint4 ent;
        ent.x = ((unsigned)s) << 6;        // byte offset of fp16 T row (32*2B)
        ent.y = packh2(m, m);              // broadcast mask as half2
        ent.z = packh2(f.x, f.y);
        ent.w = packh2(f.z, f.w);
        d_E[(long)r * CAP + pos] = ent;
    }
}

__global__ void k_fill(const int* __restrict__ send, const int* __restrict__ recv,
                       const float* __restrict__ mask, const float4* __restrict__ ef,
                       int E) {
    int base = (blockIdx.x * blockDim.x + threadIdx.x) * 8;
    if (base + 8 <= E) {
        #pragma unroll
        for (int q = 0; q < 2; q++) {
            int b = base + q * 4;
            int4 s = *(const int4*)(send + b);
            int4 r = *(const int4*)(recv + b);
            float4 m = *(const float4*)(mask + b);
            float4 f0 = ef[b], f1 = ef[b + 1], f2 = ef[b + 2], f3 = ef[b + 3];
            fill_one(s.x, r.x, m.x, f0);
            fill_one(s.y, r.y, m.y, f1);
            fill_one(s.z, r.z, m.z, f2);
            fill_one(s.w, r.w, m.w, f3);
        }
    } else {
        for (int e = base; e < E; e++)
            fill_one(send[e], recv[e], mask[e], ef[e]);
    }
}

// init: T0 = pq.x*A0 + pq.y*A1 + c0 (affine), V0=(1,0). Thread per (node, dim pair).
__global__ void k_init(const float2* __restrict__ PQ, int N) {
    __shared__ float sA0[HD], sA1[HD], sc0[HD];
    if (threadIdx.x < HD) {
        sA0[threadIdx.x] = d_A2[threadIdx.x];
        sA1[threadIdx.x] = d_A2[HD + threadIdx.x];
        sc0[threadIdx.x] = d_c0[threadIdx.x];
    }
    __syncthreads();
    int gid = blockIdx.x * blockDim.x + threadIdx.x;
    int node = gid >> 4, sub = gid & 15;
    if (node >= N) return;
    float2 pq = PQ[node];
    int d0 = 2 * sub;
    float t0 = pq.x * sA0[d0] + pq.y * sA1[d0] + sc0[d0];
    float t1 = pq.x * sA0[d0 + 1] + pq.y * sA1[d0 + 1] + sc0[d0 + 1];
    *(__half2*)&d_Th[node * HD + d0] = __floats2half2_rn(t0, t1);
    if (sub == 0) d_V[node] = make_float2(1.f, 0.f);
}

// shared epilogue: combine halves, apply S4 message term, relu, u-GEMV (FFMA2), pool
__device__ __forceinline__ void agg_epilogue(
    int w, int lane, int half, int d0, int r, bool valid,
    float s0, float s1, float sx, float sy, float sz, float sw, float sm,
    const float* sWb, const float* sb, const float* sWn,
    float sh_h[8][HD]) {
    float h0 = 0.f, h1 = 0.f;
    if (valid) {
        s0 += __shfl_xor_sync(~0u, s0, 16);
        s1 += __shfl_xor_sync(~0u, s1, 16);
        int d1 = d0 + 1;
        s0 += sx * sWb[d0] + sy * sWb[HD + d0] + sz * sWb[2 * HD + d0] +
              sw * sWb[3 * HD + d0] + sm * sb[d0];
        s1 += sx * sWb[d1] + sy * sWb[HD + d1] + sz * sWb[2 * HD + d1] +
              sw * sWb[3 * HD + d1] + sm * sb[d1];
        h0 = fmaxf(s0, 0.f);
        h1 = fmaxf(s1, 0.f);
    }
    if (lane < 16) *(float2*)&sh_h[w][d0] = valid ? make_float2(h0, h1)
                                                  : make_float2(0.f, 0.f);
    __syncwarp();
    if (valid) {
        ull uacc = 0;
        int kb = half * 16;
        #pragma unroll
        for (int kk = 0; kk < 16; kk++) {
            ull hh = bcast64(sh_h[w][kb + kk]);
            ull wv = *(const ull*)&sWn[(kb + kk) * HD + d0];
            fma2(uacc, wv, hh);
        }
        float2 u = unpack64(uacc);
        u.x += __shfl_xor_sync(~0u, u.x, 16);
        u.y += __shfl_xor_sync(~0u, u.y, 16);
        if (lane < 16) *(float2*)&d_u[r * HD + d0] = u;
    }
    __syncthreads();
    if (w == 0) {
        float ps = 0.f;
        #pragma unroll
        for (int q = 0; q < 8; q++) ps += sh_h[q][lane];
        atomicAdd(&d_pool[lane], ps);
    }
}

// aggregation (templated): HFMA2 inner loop; FIRST computes+stores S4/Smask inline
template<bool FIRST>
__global__ void __launch_bounds__(256) k_aggT(
        const float* __restrict__ W_msg, const float* __restrict__ b_msg,
        const float* __restrict__ W_n, int l, int N) {
    __shared__ float sWb[4 * HD], sb[HD], sWn[HD * HD];
    __shared__ float sh_h[8][HD];
    const float* Wl = W_msg + l * 38 * HD;
    const float* Wn = W_n + l * 64 * HD;
    for (int i = threadIdx.x; i < 4 * HD; i += blockDim.x) sWb[i] = Wl[34 * HD + i];
    for (int i = threadIdx.x; i < HD; i += blockDim.x) sb[i] = b_msg[l * HD + i];
    for (int i = threadIdx.x; i < HD * HD; i += blockDim.x) sWn[i] = Wn[i];
    __syncthreads();
    int w = threadIdx.x >> 5;
    int lane = threadIdx.x & 31;
    int half = lane >> 4, sub = lane & 15;
    int d0 = 2 * sub;
    int r = blockIdx.x * 8 + w;
    bool valid = r < N;
    float a0 = 0.f, a1 = 0.f, b0 = 0.f, b1 = 0.f;
    float sx = 0.f, sy = 0.f, sz = 0.f, sw = 0.f, sm = 0.f;
    if (valid) {
        const uint4* Eb = d_E + (long)r * CAP;
        const char* Tb = (const char*)d_Th;
        int subOff = sub * 4;
        int cnt = min(d_cursor[r], CAP);
        int p = 0;
        for (; p + 8 <= cnt; p += 8) {
            uint4 q0 = Eb[p + half];
            uint4 q1 = Eb[p + 2 + half];
            uint4 q2 = Eb[p + 4 + half];
            uint4 q3 = Eb[p + 6 + half];
            __half2 t0 = *(const __half2*)(Tb + q0.x + subOff);
            __half2 t1 = *(const __half2*)(Tb + q1.x + subOff);
            __half2 t2 = *(const __half2*)(Tb + q2.x + subOff);
            __half2 t3 = *(const __half2*)(Tb + q3.x + subOff);
            __half2 m0 = u2h(q0.y), m1 = u2h(q1.y), m2 = u2h(q2.y), m3 = u2h(q3.y);
            __half2 accA = __hmul2(m0, t0);
            accA = __hfma2(m1, t1, accA);
            __half2 accB = __hmul2(m2, t2);
            accB = __hfma2(m3, t3, accB);
            float2 fA = __half22float2(accA), fB = __half22float2(accB);
            a0 += fA.x; a1 += fA.y;
            b0 += fB.x; b1 += fB.y;
            if (FIRST) {
                __half2 s01 = __hmul2(m0, u2h(q0.z));
                s01 = __hfma2(m1, u2h(q1.z), s01);
                s01 = __hfma2(m2, u2h(q2.z), s01);
                s01 = __hfma2(m3, u2h(q3.z), s01);
                __half2 s23 = __hmul2(m0, u2h(q0.w));
                s23 = __hfma2(m1, u2h(q1.w), s23);
                s23 = __hfma2(m2, u2h(q2.w), s23);
                s23 = __hfma2(m3, u2h(q3.w), s23);
                __half2 smh = __hadd2(__hadd2(m0, m1), __hadd2(m2, m3));
                float2 f01 = __half22float2(s01), f23 = __half22float2(s23);
                sx += f01.x; sy += f01.y;
                sz += f23.x; sw += f23.y;
                sm += __low2float(smh);
            }
        }
        for (; p + 2 <= cnt; p += 2) {
            uint4 q0 = Eb[p + half];
            __half2 t0 = *(const __half2*)(Tb + q0.x + subOff);
            __half2 m0 = u2h(q0.y);
            float2 f = __half22float2(__hmul2(m0, t0));
            a0 += f.x; a1 += f.y;
            if (FIRST) {
                float2 f01 = __half22float2(__hmul2(m0, u2h(q0.z)));
                float2 f23 = __half22float2(__hmul2(m0, u2h(q0.w)));
                sx += f01.x; sy += f01.y;
                sz += f23.x; sw += f23.y;
                sm += __low2float(m0);
            }
        }
        if (p < cnt) {                     // single tail: half0 only
            uint4 q0 = Eb[p];
            if (!half) {
                __half2 t0 = *(const __half2*)(Tb + q0.x + subOff);
                __half2 m0 = u2h(q0.y);
                float2 f = __half22float2(__hmul2(m0, t0));
                b0 += f.x; b1 += f.y;
                if (FIRST) {
                    float2 f01 = __half22float2(__hmul2(m0, u2h(q0.z)));
                    float2 f23 = __half22float2(__hmul2(m0, u2h(q0.w)));
                    sx += f01.x; sy += f01.y;
                    sz += f23.x; sw += f23.y;
                    sm += __low2float(m0);
                }
            }
        }
        if (FIRST) {
            sx += __shfl_xor_sync(~0u, sx, 16);
            sy += __shfl_xor_sync(~0u, sy, 16);
            sz += __shfl_xor_sync(~0u, sz, 16);
            sw += __shfl_xor_sync(~0u, sw, 16);
            sm += __shfl_xor_sync(~0u, sm, 16);
            if (lane == 0) {
                d_S4[r] = make_float4(sx, sy, sz, sw);
                d_Smask[r] = sm;
            }
        } else {
            float4 s4 = d_S4[r];
            sx = s4.x; sy = s4.y; sz = s4.z; sw = s4.w;
            sm = d_Smask[r];
        }
    }
    agg_epilogue(w, lane, half, d0, r, valid, a0 + b0, a1 + b1,
                 sx, sy, sz, sw, sm, sWb, sb, sWn, sh_h);
}

// global supernode update + precompute c = g_new @ W_n[32:64] + b_n ; re-zero pool
__global__ void k_g(const float* __restrict__ W_g, const float* __restrict__ b_g,
                    const float* __restrict__ W_n, const float* __restrict__ b_n,
                    int l, int N) {
    int j = threadIdx.x;  // 32 threads
    float p = d_pool[j] / (float)N;
    d_pool[j] = 0.f;
    float gold = d_g[j];
    const float* Wg = W_g + l * 64 * HD;
    float acc = b_g[l * HD + j];
    #pragma unroll
    for (int k = 0; k < HD; k++) {
        acc += __shfl_sync(~0u, gold, k) * Wg[k * HD + j];
        acc += __shfl_sync(~0u, p, k) * Wg[(HD + k) * HD + j];
    }
    float gn = fmaxf(acc, 0.f);
    d_g[j] = gn;
    const float* Wn = W_n + l * 64 * HD;
    float c = b_n[l * HD + j];
    #pragma unroll
    for (int k = 0; k < HD; k++)
        c += __shfl_sync(~0u, gn, k) * Wn[(HD + k) * HD + j];
    d_c[j] = c;
}

// node update: hn = relu(u + c); V += hn@W_out + b_out; T_next = [V,hn]@W_top(l+1)
__global__ void k_node(const float* __restrict__ W_out, const float* __restrict__ b_out,
                       const float* __restrict__ W_msg,
                       int l, int N, int last, float2* __restrict__ outV) {
    __shared__ float sWo[HD * 2], sWt[34 * HD], sc[HD];
    for (int i = threadIdx.x; i < HD * 2; i += blockDim.x) sWo[i] = W_out[l * HD * 2 + i];
    if (!last) {
        const float* Wt = W_msg + (l + 1) * 38 * HD;
        for (int i = threadIdx.x; i < 34 * HD; i += blockDim.x) sWt[i] = Wt[i];
    }
    for (int i = threadIdx.x; i < HD; i += blockDim.x) sc[i] = d_c[i];
    __syncthreads();
    int r = (blockIdx.x * blockDim.x + threadIdx.x) >> 5;
    int lane = threadIdx.x & 31;
    if (r >= N) return;
    float hn = fmaxf(d_u[r * HD + lane] + sc[lane], 0.f);
    float v0 = hn * sWo[lane * 2 + 0];
    float v1 = hn * sWo[lane * 2 + 1];
    #pragma unroll
    for (int o = 16; o; o >>= 1) {
        v0 += __shfl_xor_sync(~0u, v0, o);
        v1 += __shfl_xor_sync(~0u, v1, o);
    }
    float2 v = d_V[r];
    v.x += v0 + b_out[l * 2 + 0];
    v.y += v1 + b_out[l * 2 + 1];
    if (last) {
        if (lane == 0) outV[r] = v;
    } else {
        if (lane == 0) d_V[r] = v;
        int half = lane >> 4, sub = lane & 15;
        int d0 = 2 * sub, d1 = d0 + 1;
        int kb = half * 16;
        ull tacc = 0;
        #pragma unroll
        for (int kk = 0; kk < 16; kk++) {
            float hk = __shfl_sync(~0u, hn, kb + kk);
            ull wv = *(const ull*)&sWt[(2 + kb + kk) * HD + d0];
            fma2(tacc, wv, bcast64(hk));
        }
        float2 t = unpack64(tacc);
        t.x += __shfl_xor_sync(~0u, t.x, 16);
        t.y += __shfl_xor_sync(~0u, t.y, 16);
        t.x += v.x * sWt[d0] + v.y * sWt[HD + d0];
        t.y += v.x * sWt[d1] + v.y * sWt[HD + d1];
        if (lane < 16)
            *(__half2*)&d_Th[r * HD + d0] = __floats2half2_rn(t.x, t.y);
    }
}

// ---------------- launch ----------------
extern "C" void kernel_launch(void* const* d_in, const int* in_sizes, int n_in,
                              void* d_out, int out_size) {
    const float2* PQ    = (const float2*)d_in[0];
    const int*    send  = (const int*)d_in[1];
    const int*    recv  = (const int*)d_in[2];
    const float4* ef    = (const float4*)d_in[3];
    const float*  mask  = (const float*)d_in[4];
    const float*  W_in  = (const float*)d_in[5];
    const float*  b_in  = (const float*)d_in[6];
    const float*  W_msg = (const float*)d_in[7];
    const float*  b_msg = (const float*)d_in[8];
    const float*  W_g   = (const float*)d_in[9];
    const float*  b_g   = (const float*)d_in[10];
    const float*  W_n   = (const float*)d_in[11];
    const float*  b_n   = (const float*)d_in[12];
    const float*  W_out = (const float*)d_in[13];
    const float*  b_out = (const float*)d_in[14];

    int N = in_sizes[0] / 2;
    int E = in_sizes[1];
    int nwb = (N + 7) / 8;          // warp-per-node kernels (256 thr)
    int eb8 = (E + 2047) / 2048;    // 8 edges/thread

    k_zero<<<(N + 255) / 256, 256>>>(W_in, b_in, W_msg, N);
    k_fill<<<eb8, 256>>>(send, recv, mask, ef, E);
    k_init<<<(N * 16 + 255) / 256, 256>>>(PQ, N);

    k_aggT<true><<<nwb, 256>>>(W_msg, b_msg, W_n, 0, N);
    k_g<<<1, 32>>>(W_g, b_g, W_n, b_n, 0, N);
    k_node<<<nwb, 256>>>(W_out, b_out, W_msg, 0, N, 0, (float2*)d_out);

    for (int l = 1; l < 3; l++) {
        k_aggT<false><<<nwb, 256>>>(W_msg, b_msg, W_n, l, N);
        k_g<<<1, 32>>>(W_g, b_g, W_n, b_n, l, N);
        k_node<<<nwb, 256>>>(W_out, b_out, W_msg, l, N, l == 2, (float2*)d_out);
    }
}

// round 11
// speedup vs baseline: 1.0638x; 1.0036x over previous
#include <cuda_runtime.h>
#include <cuda_fp16.h>

#define NMAX 100000
#define HD 32
#define CAP 80

typedef unsigned long long ull;

// ---------------- scratch (static __device__, no allocation) ----------------
__device__ __align__(16) __half d_Th[NMAX * HD];  // fp16 per-node transform [V,h]@W_top
__device__ __align__(16) float  d_u[NMAX * HD];   // h @ W_n_top (pre-relu node update)
__device__ float2 d_V[NMAX];                      // running V
__device__ __align__(16) uint4  d_E[(long)NMAX * CAP]; // {soff(=s*64), h2(m,m), h2(ef01), h2(ef23)}
__device__ int    d_cursor[NMAX];                 // per-receiver count (atomic)
__device__ __align__(16) float4 d_S4[NMAX];       // sum(mask*ef) per receiver
__device__ float  d_Smask[NMAX];                  // sum(mask) per receiver
__device__ float  d_pool[HD];                     // atomic pooled sum of h
__device__ float  d_g[HD];                        // global supernode state
__device__ float  d_c[HD];                        // g@W_n_bot + b_n (per layer)
__device__ float  d_A2[2 * HD];                   // init affine map rows
__device__ float  d_c0[HD];                       // init affine bias

__device__ __forceinline__ unsigned packh2(float a, float b) {
    __half2 h = __floats2half2_rn(a, b);
    return *reinterpret_cast<unsigned*>(&h);
}
__device__ __forceinline__ __half2 u2h(unsigned u) {
    return *reinterpret_cast<__half2*>(&u);
}
__device__ __forceinline__ ull bcast64(float a) {        // {a,a} packed
    ull r; asm("mov.b64 %0, {%1, %1};" : "=l"(r) : "f"(a)); return r;
}
__device__ __forceinline__ void fma2(ull& acc, ull a, ull b) {
    asm("fma.rn.f32x2 %0, %1, %2, %0;" : "+l"(acc) : "l"(a), "l"(b));
}
__device__ __forceinline__ float2 unpack64(ull v) {
    float2 f; asm("mov.b64 {%0, %1}, %2;" : "=f"(f.x), "=f"(f.y) : "l"(v)); return f;
}

// ---------------- zero + init-affine prep ----------------
__global__ void k_zero(const float* __restrict__ W_in, const float* __restrict__ b_in,
                       const float* __restrict__ W_msg, int N) {
    int i = blockIdx.x * blockDim.x + threadIdx.x;
    if (i < N) d_cursor[i] = 0;
    if (blockIdx.x == 0 && threadIdx.x < HD) {
        int j = threadIdx.x;
        d_g[j] = 0.f; d_pool[j] = 0.f;
        const float* Wt = W_msg;       // layer 0 top rows (34 x 32)
        float c0 = Wt[j];              // V0=(1,0) -> + Wt[0][j]
        float a0 = 0.f, a1 = 0.f;
        for (int k = 0; k < HD; k++) {
            float wt = Wt[(2 + k) * HD + j];
            c0 += b_in[k] * wt;
            a0 += W_in[k] * wt;
            a1 += W_in[HD + k] * wt;
        }
        d_A2[j] = a0; d_A2[HD + j] = a1; d_c0[j] = c0;
    }
}

// ---------------- bucket fill: 1 atomic + one 16B store per edge ----------------
__device__ __forceinline__ void fill_one(int s, int r, float m, float4 f) {
    int pos = atomicAdd(&d_cursor[r], 1);
    if (pos < CAP) {
        uint4 ent;
        ent.x = ((unsigned)s) << 6;        // byte offset of fp16 T row (32*2B)
        ent.y = packh2(m, m);              // broadcast mask as half2
        ent.z = packh2(f.x, f.y);
        ent.w = packh2(f.z, f.w);
        d_E[(long)r * CAP + pos] = ent;
    }
}

__global__ void k_fill(const int* __restrict__ send, const int* __restrict__ recv,
                       const float* __restrict__ mask, const float4* __restrict__ ef,
                       int E) {
    int base = (blockIdx.x * blockDim.x + threadIdx.x) * 8;
    if (base + 8 <= E) {
        #pragma unroll
        for (int q = 0; q < 2; q++) {
            int b = base + q * 4;
            int4 s = *(const int4*)(send + b);
            int4 r = *(const int4*)(recv + b);
            float4 m = *(const float4*)(mask + b);
            float4 f0 = ef[b], f1 = ef[b + 1], f2 = ef[b + 2], f3 = ef[b + 3];
            fill_one(s.x, r.x, m.x, f0);
            fill_one(s.y, r.y, m.y, f1);
            fill_one(s.z, r.z, m.z, f2);
            fill_one(s.w, r.w, m.w, f3);
        }
    } else {
        for (int e = base; e < E; e++)
            fill_one(send[e], recv[e], mask[e], ef[e]);
    }
}

// init: T0 = pq.x*A0 + pq.y*A1 + c0 (affine), V0=(1,0). Thread per (node, dim pair).
__global__ void k_init(const float2* __restrict__ PQ, int N) {
    __shared__ float sA0[HD], sA1[HD], sc0[HD];
    if (threadIdx.x < HD) {
        sA0[threadIdx.x] = d_A2[threadIdx.x];
        sA1[threadIdx.x] = d_A2[HD + threadIdx.x];
        sc0[threadIdx.x] = d_c0[threadIdx.x];
    }
    __syncthreads();
    int gid = blockIdx.x * blockDim.x + threadIdx.x;
    int node = gid >> 4, sub = gid & 15;
    if (node >= N) return;
    float2 pq = PQ[node];
    int d0 = 2 * sub;
    float t0 = pq.x * sA0[d0] + pq.y * sA1[d0] + sc0[d0];
    float t1 = pq.x * sA0[d0 + 1] + pq.y * sA1[d0 + 1] + sc0[d0 + 1];
    *(__half2*)&d_Th[node * HD + d0] = __floats2half2_rn(t0, t1);
    if (sub == 0) d_V[node] = make_float2(1.f, 0.f);
}

// shared epilogue: combine halves, apply S4 message term, relu, u-GEMV (FFMA2), pool
__device__ __forceinline__ void agg_epilogue(
    int w, int lane, int half, int d0, int r, bool valid,
    float s0, float s1, float sx, float sy, float sz, float sw, float sm,
    const float* sWb, const float* sb, const float* sWn,
    float sh_h[8][HD]) {
    float h0 = 0.f, h1 = 0.f;
    if (valid) {
        s0 += __shfl_xor_sync(~0u, s0, 16);
        s1 += __shfl_xor_sync(~0u, s1, 16);
        int d1 = d0 + 1;
        s0 += sx * sWb[d0] + sy * sWb[HD + d0] + sz * sWb[2 * HD + d0] +
              sw * sWb[3 * HD + d0] + sm * sb[d0];
        s1 += sx * sWb[d1] + sy * sWb[HD + d1] + sz * sWb[2 * HD + d1] +
              sw * sWb[3 * HD + d1] + sm * sb[d1];
        h0 = fmaxf(s0, 0.f);
        h1 = fmaxf(s1, 0.f);
    }
    if (lane < 16) *(float2*)&sh_h[w][d0] = valid ? make_float2(h0, h1)
                                                  : make_float2(0.f, 0.f);
    __syncwarp();
    if (valid) {
        ull uacc = 0;
        int kb = half * 16;
        #pragma unroll
        for (int kk = 0; kk < 16; kk++) {
            ull hh = bcast64(sh_h[w][kb + kk]);
            ull wv = *(const ull*)&sWn[(kb + kk) * HD + d0];
            fma2(uacc, wv, hh);
        }
        float2 u = unpack64(uacc);
        u.x += __shfl_xor_sync(~0u, u.x, 16);
        u.y += __shfl_xor_sync(~0u, u.y, 16);
        if (lane < 16) *(float2*)&d_u[r * HD + d0] = u;
    }
    __syncthreads();
    if (w == 0) {
        float ps = 0.f;
        #pragma unroll
        for (int q = 0; q < 8; q++) ps += sh_h[q][lane];
        atomicAdd(&d_pool[lane], ps);
    }
}

// aggregation: warp-wide entry prefetch -> smem staging -> latency-decoupled gathers.
// FIRST also computes S4/Smask per-lane in the prefetch phase (butterfly reduce).
template<bool FIRST>
__global__ void __launch_bounds__(256) k_aggT(
        const float* __restrict__ W_msg, const float* __restrict__ b_msg,
        const float* __restrict__ W_n, int l, int N) {
    __shared__ float sWb[4 * HD], sb[HD], sWn[HD * HD];
    __shared__ float sh_h[8][HD];
    __shared__ __align__(16) uint2 s_ent[8][2][16];  // [warp][parity][pairIdx]
    const float* Wl = W_msg + l * 38 * HD;
    const float* Wn = W_n + l * 64 * HD;
    for (int i = threadIdx.x; i < 4 * HD; i += blockDim.x) sWb[i] = Wl[34 * HD + i];
    for (int i = threadIdx.x; i < HD; i += blockDim.x) sb[i] = b_msg[l * HD + i];
    for (int i = threadIdx.x; i < HD * HD; i += blockDim.x) sWn[i] = Wn[i];
    __syncthreads();
    int w = threadIdx.x >> 5;
    int lane = threadIdx.x & 31;
    int half = lane >> 4, sub = lane & 15;
    int d0 = 2 * sub;
    int r = blockIdx.x * 8 + w;
    bool valid = r < N;
    float a0 = 0.f, a1 = 0.f, b0 = 0.f, b1 = 0.f;
    float sx = 0.f, sy = 0.f, sz = 0.f, sw = 0.f, sm = 0.f;
    if (valid) {
        const uint4* Eb = d_E + (long)r * CAP;
        const char* Tb = (const char*)d_Th;
        int subOff = sub * 4;
        int cnt = min(d_cursor[r], CAP);
        for (int base = 0; base < cnt; base += 32) {
            int c = min(32, cnt - base);
            // phase A: warp-wide entry fetch (full MLP on the long-latency load)
            if (lane < c) {
                uint4 q = Eb[base + lane];
                if (FIRST) {
                    __half2 m = u2h(q.y);
                    float2 f01 = __half22float2(__hmul2(m, u2h(q.z)));
                    float2 f23 = __half22float2(__hmul2(m, u2h(q.w)));
                    sx += f01.x; sy += f01.y;
                    sz += f23.x; sw += f23.y;
                    sm += __low2float(m);
                }
                s_ent[w][lane & 1][lane >> 1] = make_uint2(q.x, q.y);
            }
            __syncwarp();
            // phase B: gathers decoupled via LDS (29cyc) instead of entry LDG (600cyc)
            int npair = c >> 1;
            int i = 0;
            for (; i + 2 <= npair; i += 2) {
                uint4 two = *(const uint4*)&s_ent[w][half][i];  // 2 pair entries
                __half2 t0 = *(const __half2*)(Tb + two.x + subOff);
                __half2 t1 = *(const __half2*)(Tb + two.z + subOff);
                __half2 acc = __hfma2(u2h(two.w), t1, __hmul2(u2h(two.y), t0));
                float2 f = __half22float2(acc);
                a0 += f.x; a1 += f.y;
            }
            if (i < npair) {
                uint2 e = s_ent[w][half][i];
                __half2 t0 = *(const __half2*)(Tb + e.x + subOff);
                float2 f = __half22float2(__hmul2(u2h(e.y), t0));
                b0 += f.x; b1 += f.y;
            }
            if (c & 1) {                       // odd tail entry c-1 (parity 0): half0 only
                uint2 e = s_ent[w][0][(c - 1) >> 1];
                if (!half) {
                    __half2 t0 = *(const __half2*)(Tb + e.x + subOff);
                    float2 f = __half22float2(__hmul2(u2h(e.y), t0));
                    b0 += f.x; b1 += f.y;
                }
            }
            __syncwarp();
        }
        if (FIRST) {
            #pragma unroll
            for (int o = 16; o; o >>= 1) {
                sx += __shfl_xor_sync(~0u, sx, o);
                sy += __shfl_xor_sync(~0u, sy, o);
                sz += __shfl_xor_sync(~0u, sz, o);
                sw += __shfl_xor_sync(~0u, sw, o);
                sm += __shfl_xor_sync(~0u, sm, o);
            }
            if (lane == 0) {
                d_S4[r] = make_float4(sx, sy, sz, sw);
                d_Smask[r] = sm;
            }
        } else {
            float4 s4 = d_S4[r];
            sx = s4.x; sy = s4.y; sz = s4.z; sw = s4.w;
            sm = d_Smask[r];
        }
    }
    agg_epilogue(w, lane, half, d0, r, valid, a0 + b0, a1 + b1,
                 sx, sy, sz, sw, sm, sWb, sb, sWn, sh_h);
}

// global supernode update + precompute c = g_new @ W_n[32:64] + b_n ; re-zero pool
__global__ void k_g(const float* __restrict__ W_g, const float* __restrict__ b_g,
                    const float* __restrict__ W_n, const float* __restrict__ b_n,
                    int l, int N) {
    int j = threadIdx.x;  // 32 threads
    float p = d_pool[j] / (float)N;
    d_pool[j] = 0.f;
    float gold = d_g[j];
    const float* Wg = W_g + l * 64 * HD;
    float acc = b_g[l * HD + j];
    #pragma unroll
    for (int k = 0; k < HD; k++) {
        acc += __shfl_sync(~0u, gold, k) * Wg[k * HD + j];
        acc += __shfl_sync(~0u, p, k) * Wg[(HD + k) * HD + j];
    }
    float gn = fmaxf(acc, 0.f);
    d_g[j] = gn;
    const float* Wn = W_n + l * 64 * HD;
    float c = b_n[l * HD + j];
    #pragma unroll
    for (int k = 0; k < HD; k++)
        c += __shfl_sync(~0u, gn, k) * Wn[(HD + k) * HD + j];
    d_c[j] = c;
}

// node update: hn = relu(u + c); V += hn@W_out + b_out; T_next = [V,hn]@W_top(l+1)
__global__ void k_node(const float* __restrict__ W_out, const float* __restrict__ b_out,
                       const float* __restrict__ W_msg,
                       int l, int N, int last, float2* __restrict__ outV) {
    __shared__ float sWo[HD * 2], sWt[34 * HD], sc[HD];
    for (int i = threadIdx.x; i < HD * 2; i += blockDim.x) sWo[i] = W_out[l * HD * 2 + i];
    if (!last) {
        const float* Wt = W_msg + (l + 1) * 38 * HD;
        for (int i = threadIdx.x; i < 34 * HD; i += blockDim.x) sWt[i] = Wt[i];
    }
    for (int i = threadIdx.x; i < HD; i += blockDim.x) sc[i] = d_c[i];
    __syncthreads();
    int r = (blockIdx.x * blockDim.x + threadIdx.x) >> 5;
    int lane = threadIdx.x & 31;
    if (r >= N) return;
    float hn = fmaxf(d_u[r * HD + lane] + sc[lane], 0.f);
    float v0 = hn * sWo[lane * 2 + 0];
    float v1 = hn * sWo[lane * 2 + 1];
    #pragma unroll
    for (int o = 16; o; o >>= 1) {
        v0 += __shfl_xor_sync(~0u, v0, o);
        v1 += __shfl_xor_sync(~0u, v1, o);
    }
    float2 v = d_V[r];
    v.x += v0 + b_out[l * 2 + 0];
    v.y += v1 + b_out[l * 2 + 1];
    if (last) {
        if (lane == 0) outV[r] = v;
    } else {
        if (lane == 0) d_V[r] = v;
        int half = lane >> 4, sub = lane & 15;
        int d0 = 2 * sub, d1 = d0 + 1;
        int kb = half * 16;
        ull tacc = 0;
        #pragma unroll
        for (int kk = 0; kk < 16; kk++) {
            float hk = __shfl_sync(~0u, hn, kb + kk);
            ull wv = *(const ull*)&sWt[(2 + kb + kk) * HD + d0];
            fma2(tacc, wv, bcast64(hk));
        }
        float2 t = unpack64(tacc);
        t.x += __shfl_xor_sync(~0u, t.x, 16);
        t.y += __shfl_xor_sync(~0u, t.y, 16);
        t.x += v.x * sWt[d0] + v.y * sWt[HD + d0];
        t.y += v.x * sWt[d1] + v.y * sWt[HD + d1];
        if (lane < 16)
            *(__half2*)&d_Th[r * HD + d0] = __floats2half2_rn(t.x, t.y);
    }
}

// ---------------- launch ----------------
extern "C" void kernel_launch(void* const* d_in, const int* in_sizes, int n_in,
                              void* d_out, int out_size) {
    const float2* PQ    = (const float2*)d_in[0];
    const int*    send  = (const int*)d_in[1];
    const int*    recv  = (const int*)d_in[2];
    const float4* ef    = (const float4*)d_in[3];
    const float*  mask  = (const float*)d_in[4];
    const float*  W_in  = (const float*)d_in[5];
    const float*  b_in  = (const float*)d_in[6];
    const float*  W_msg = (const float*)d_in[7];
    const float*  b_msg = (const float*)d_in[8];
    const float*  W_g   = (const float*)d_in[9];
    const float*  b_g   = (const float*)d_in[10];
    const float*  W_n   = (const float*)d_in[11];
    const float*  b_n   = (const float*)d_in[12];
    const float*  W_out = (const float*)d_in[13];
    const float*  b_out = (const float*)d_in[14];

    int N = in_sizes[0] / 2;
    int E = in_sizes[1];
    int nwb = (N + 7) / 8;          // warp-per-node kernels (256 thr)
    int eb8 = (E + 2047) / 2048;    // 8 edges/thread

    k_zero<<<(N + 255) / 256, 256>>>(W_in, b_in, W_msg, N);
    k_fill<<<eb8, 256>>>(send, recv, mask, ef, E);
    k_init<<<(N * 16 + 255) / 256, 256>>>(PQ, N);

    k_aggT<true><<<nwb, 256>>>(W_msg, b_msg, W_n, 0, N);
    k_g<<<1, 32>>>(W_g, b_g, W_n, b_n, 0, N);
    k_node<<<nwb, 256>>>(W_out, b_out, W_msg, 0, N, 0, (float2*)d_out);

    for (int l = 1; l < 3; l++) {
        k_aggT<false><<<nwb, 256>>>(W_msg, b_msg, W_n, l, N);
        k_g<<<1, 32>>>(W_g, b_g, W_n, b_n, l, N);
        k_node<<<nwb, 256>>>(W_out, b_out, W_msg, l, N, l == 2, (float2*)d_out);
    }
}